// round 8
// baseline (speedup 1.0000x reference)
#include <cuda_runtime.h>
#include <cuda_fp16.h>
#include <stdint.h>

#define NB 4
#define CH 128
#define HW 4096
#define BT 128
#define BS 64
#define THREADS 256
#define QK_PITCH 136   // 128 + 8 halfs: row stride 272B -> conflict-free ldmatrix phases
#define V_PITCH 72     // 64 + 8 halfs: row stride 144B -> conflict-free ldmatrix phases

__device__ __forceinline__ void mma16816(float c[4], const uint32_t a[4],
                                         uint32_t b0, uint32_t b1) {
    asm volatile(
        "mma.sync.aligned.m16n8k16.row.col.f32.f16.f16.f32 "
        "{%0,%1,%2,%3}, {%4,%5,%6,%7}, {%8,%9}, {%0,%1,%2,%3};\n"
        : "+f"(c[0]), "+f"(c[1]), "+f"(c[2]), "+f"(c[3])
        : "r"(a[0]), "r"(a[1]), "r"(a[2]), "r"(a[3]), "r"(b0), "r"(b1));
}

__device__ __forceinline__ void ldsm_x4(uint32_t& r0, uint32_t& r1,
                                        uint32_t& r2, uint32_t& r3, uint32_t addr) {
    asm volatile("ldmatrix.sync.aligned.m8n8.x4.shared.b16 {%0,%1,%2,%3}, [%4];"
                 : "=r"(r0), "=r"(r1), "=r"(r2), "=r"(r3) : "r"(addr));
}

__device__ __forceinline__ float ex2(float x) {
    float y;
    asm("ex2.approx.ftz.f32 %0, %1;" : "=f"(y) : "f"(x));
    return y;
}

__device__ __forceinline__ uint32_t packh2(float a, float b) {
    __half2 h = __floats2half2_rn(a, b);
    return *reinterpret_cast<uint32_t*>(&h);
}

__global__ void __launch_bounds__(THREADS, 1)
attn_kernel(const float* __restrict__ Kg, const float* __restrict__ Qg,
            const float* __restrict__ Vg, float* __restrict__ Og) {
    extern __shared__ __half smem[];
    __half* Qs = smem;                   // [BT][QK_PITCH]  (t, c)
    __half* Ks = Qs + BT * QK_PITCH;     // [BS][QK_PITCH]  (s, c)
    __half* Vs = Ks + BS * QK_PITCH;     // [CH][V_PITCH]   (e, s)

    const int n  = blockIdx.y;
    const int t0 = blockIdx.x * BT;
    const size_t base = (size_t)n * CH * HW;
    const float* kb = Kg + base;
    const float* qb = Qg + base;
    const float* vb = Vg + base;
    float* ob = Og + base;

    const int tid  = threadIdx.x;
    const int warp = tid >> 5;
    const int lane = tid & 31;
    const int g    = lane >> 2;   // groupID (row within fragment)
    const int tq   = lane & 3;    // thread-in-group (col pairs)

    // ---- load Q tile transposed: q[c][t0+t] -> Qs[t][c], fp32 -> fp16
    for (int i = tid; i < CH * BT / 4; i += THREADS) {
        int c = i >> 5;
        int t = (i & 31) << 2;
        float4 f = *reinterpret_cast<const float4*>(&qb[(size_t)c * HW + t0 + t]);
        Qs[(t + 0) * QK_PITCH + c] = __float2half(f.x);
        Qs[(t + 1) * QK_PITCH + c] = __float2half(f.y);
        Qs[(t + 2) * QK_PITCH + c] = __float2half(f.z);
        Qs[(t + 3) * QK_PITCH + c] = __float2half(f.w);
    }
    __syncthreads();

    // ---- per-lane ldmatrix base addresses ----
    // A-frag mapping (x4): m0=(r,k) m1=(r+8,k) m2=(r,k+8) m3=(r+8,k+8)
    //   lane L: row += (L>>3 & 1)*8, k += (L>>4 & 1)*8, base row = L&7
    // B-frag mapping (x4): m0=(n,k) m1=(n,k+8) m2=(n+8,k) m3=(n+8,k+8)
    //   lane L: n += (L>>4 & 1)*8, k += (L>>3 & 1)*8, base n = L&7
    const int l7   = lane & 7;
    const int bit3 = (lane >> 3) & 1;
    const int bit4 = (lane >> 4) & 1;

    const uint32_t qs_u32 = (uint32_t)__cvta_generic_to_shared(Qs);
    const uint32_t ks_u32 = (uint32_t)__cvta_generic_to_shared(Ks);
    const uint32_t vs_u32 = (uint32_t)__cvta_generic_to_shared(Vs);

    const uint32_t qa_lane = qs_u32 +
        (uint32_t)(((warp * 16 + l7 + bit3 * 8) * QK_PITCH + bit4 * 8) * 2);
    const uint32_t kb_lane = ks_u32 +
        (uint32_t)(((l7 + bit4 * 8) * QK_PITCH + bit3 * 8) * 2);
    const uint32_t vb_lane = vs_u32 +
        (uint32_t)(((l7 + bit4 * 8) * V_PITCH + bit3 * 8) * 2);

    // ---- Q A-fragments resident in registers: warp owns rows warp*16 .. +15
    uint32_t qa[8][4];
    #pragma unroll
    for (int kk = 0; kk < 8; kk++)
        ldsm_x4(qa[kk][0], qa[kk][1], qa[kk][2], qa[kk][3],
                qa_lane + (uint32_t)(16 * kk * 2));

    // log2(e) / sqrt(128): folds both the 1/sqrt(c) scale and base-2 exp
    const float kf = 0.12751742562077963f;

    float mrow0 = -1e30f, mrow1 = -1e30f;   // running max, rows g and g+8
    float lrow0 = 0.f, lrow1 = 0.f;         // running sum
    float o[16][4];
    #pragma unroll
    for (int j = 0; j < 16; j++)
        o[j][0] = o[j][1] = o[j][2] = o[j][3] = 0.f;

    for (int s0 = 0; s0 < HW; s0 += BS) {
        __syncthreads();   // previous tile's smem reads done before overwrite
        // K tile: k[c][s0+s] -> Ks[s][c] (transpose)
        for (int i = tid; i < CH * BS / 4; i += THREADS) {
            int c = i >> 4;
            int s = (i & 15) << 2;
            float4 f = *reinterpret_cast<const float4*>(&kb[(size_t)c * HW + s0 + s]);
            Ks[(s + 0) * QK_PITCH + c] = __float2half(f.x);
            Ks[(s + 1) * QK_PITCH + c] = __float2half(f.y);
            Ks[(s + 2) * QK_PITCH + c] = __float2half(f.z);
            Ks[(s + 3) * QK_PITCH + c] = __float2half(f.w);
        }
        // V tile: v[e][s0+s] -> Vs[e][s] (layout preserved; B col-major for PV)
        for (int i = tid; i < CH * BS / 4; i += THREADS) {
            int e = i >> 4;
            int s = (i & 15) << 2;
            float4 f = *reinterpret_cast<const float4*>(&vb[(size_t)e * HW + s0 + s]);
            __half2* dst = reinterpret_cast<__half2*>(&Vs[e * V_PITCH + s]);
            dst[0] = __floats2half2_rn(f.x, f.y);
            dst[1] = __floats2half2_rn(f.z, f.w);
        }
        __syncthreads();

        // ---- S = Q·K^T for this warp's 16 rows x 64 cols (ldmatrix-fed)
        float sacc[8][4];
        #pragma unroll
        for (int j = 0; j < 8; j++)
            sacc[j][0] = sacc[j][1] = sacc[j][2] = sacc[j][3] = 0.f;

        #pragma unroll
        for (int kk = 0; kk < 8; kk++) {
            #pragma unroll
            for (int jp = 0; jp < 4; jp++) {   // j pair = (2jp, 2jp+1)
                uint32_t b00, b01, b10, b11;
                ldsm_x4(b00, b01, b10, b11,
                        kb_lane + (uint32_t)((16 * jp * QK_PITCH + 16 * kk) * 2));
                mma16816(sacc[2 * jp],     qa[kk], b00, b01);
                mma16816(sacc[2 * jp + 1], qa[kk], b10, b11);
            }
        }

        // ---- online softmax (raw-dot domain; kf applies scale+log2e inside ex2)
        float mx0 = -1e30f, mx1 = -1e30f;
        #pragma unroll
        for (int j = 0; j < 8; j++) {
            mx0 = fmaxf(mx0, fmaxf(sacc[j][0], sacc[j][1]));
            mx1 = fmaxf(mx1, fmaxf(sacc[j][2], sacc[j][3]));
        }
        mx0 = fmaxf(mx0, __shfl_xor_sync(0xffffffffu, mx0, 1));
        mx0 = fmaxf(mx0, __shfl_xor_sync(0xffffffffu, mx0, 2));
        mx1 = fmaxf(mx1, __shfl_xor_sync(0xffffffffu, mx1, 1));
        mx1 = fmaxf(mx1, __shfl_xor_sync(0xffffffffu, mx1, 2));

        float mn0 = fmaxf(mrow0, mx0);
        float mn1 = fmaxf(mrow1, mx1);
        float alpha0 = ex2(kf * (mrow0 - mn0));
        float alpha1 = ex2(kf * (mrow1 - mn1));
        mrow0 = mn0; mrow1 = mn1;

        float rs0 = 0.f, rs1 = 0.f;
        #pragma unroll
        for (int j = 0; j < 8; j++) {
            sacc[j][0] = ex2(kf * (sacc[j][0] - mn0));
            sacc[j][1] = ex2(kf * (sacc[j][1] - mn0));
            sacc[j][2] = ex2(kf * (sacc[j][2] - mn1));
            sacc[j][3] = ex2(kf * (sacc[j][3] - mn1));
            rs0 += sacc[j][0] + sacc[j][1];
            rs1 += sacc[j][2] + sacc[j][3];
        }
        rs0 += __shfl_xor_sync(0xffffffffu, rs0, 1);
        rs0 += __shfl_xor_sync(0xffffffffu, rs0, 2);
        rs1 += __shfl_xor_sync(0xffffffffu, rs1, 1);
        rs1 += __shfl_xor_sync(0xffffffffu, rs1, 2);
        lrow0 = lrow0 * alpha0 + rs0;
        lrow1 = lrow1 * alpha1 + rs1;

        #pragma unroll
        for (int j = 0; j < 16; j++) {
            o[j][0] *= alpha0; o[j][1] *= alpha0;
            o[j][2] *= alpha1; o[j][3] *= alpha1;
        }

        // ---- P (C-frag layout) -> A-fragments for PV mma
        uint32_t pa[4][4];
        #pragma unroll
        for (int kk = 0; kk < 4; kk++) {
            pa[kk][0] = packh2(sacc[2 * kk][0],     sacc[2 * kk][1]);
            pa[kk][1] = packh2(sacc[2 * kk][2],     sacc[2 * kk][3]);
            pa[kk][2] = packh2(sacc[2 * kk + 1][0], sacc[2 * kk + 1][1]);
            pa[kk][3] = packh2(sacc[2 * kk + 1][2], sacc[2 * kk + 1][3]);
        }

        // ---- O += P·V   (B = V stored (e,s) row-major == (s,e) col-major)
        #pragma unroll
        for (int kk = 0; kk < 4; kk++) {
            #pragma unroll
            for (int jep = 0; jep < 8; jep++) {  // je pair = (2jep, 2jep+1)
                uint32_t b00, b01, b10, b11;
                ldsm_x4(b00, b01, b10, b11,
                        vb_lane + (uint32_t)((16 * jep * V_PITCH + 16 * kk) * 2));
                mma16816(o[2 * jep],     pa[kk], b00, b01);
                mma16816(o[2 * jep + 1], pa[kk], b10, b11);
            }
        }
    }

    // ---- normalize and write transposed output out[n][e][t]
    float inv0 = 1.f / lrow0;
    float inv1 = 1.f / lrow1;
    int r = t0 + warp * 16 + g;
    #pragma unroll
    for (int je = 0; je < 16; je++) {
        int e = 8 * je + 2 * tq;
        ob[(size_t)e * HW + r]             = o[je][0] * inv0;
        ob[(size_t)(e + 1) * HW + r]       = o[je][1] * inv0;
        ob[(size_t)e * HW + r + 8]         = o[je][2] * inv1;
        ob[(size_t)(e + 1) * HW + r + 8]   = o[je][3] * inv1;
    }
}

extern "C" void kernel_launch(void* const* d_in, const int* in_sizes, int n_in,
                              void* d_out, int out_size) {
    const float* k = (const float*)d_in[0];   // key
    const float* q = (const float*)d_in[1];   // query
    const float* v = (const float*)d_in[2];   // value
    float* o = (float*)d_out;

    size_t smem_bytes = (size_t)(BT * QK_PITCH + BS * QK_PITCH + CH * V_PITCH) * sizeof(__half);
    cudaFuncSetAttribute((const void*)attn_kernel,
                         cudaFuncAttributeMaxDynamicSharedMemorySize, (int)smem_bytes);
    dim3 grid(HW / BT, NB);
    attn_kernel<<<grid, THREADS, (int)smem_bytes>>>(k, q, v, o);
}

// round 9
// speedup vs baseline: 2.4972x; 2.4972x over previous
#include <cuda_runtime.h>
#include <cuda_fp16.h>
#include <stdint.h>

#define NB 4
#define CH 128
#define HW 4096
#define BT 128
#define BS 64
#define THREADS 256
#define NTILES (HW / BS)
#define QK_PITCH 136   // halfs; row stride 272B (17x16B): 16B-aligned, conflict-free frag reads
#define V_PITCH 72     // halfs; row stride 144B (9x16B)

// fp16 scratch: Q,K transposed to [n][t][c]; V converted, layout kept [n][e][s]
__device__ __half g_qt[(size_t)NB * HW * CH];
__device__ __half g_kt[(size_t)NB * HW * CH];
__device__ __half g_vh[(size_t)NB * CH * HW];

// ---------------- pre-pass kernels ----------------

// in: [n][c][t] fp32  ->  out: [n][t][c] fp16   (which: 0 -> g_qt, 1 -> g_kt)
__global__ void transpose_f32f16(const float* __restrict__ in, int which) {
    __shared__ float tile[32][33];
    const int n  = blockIdx.z;
    const int t0 = blockIdx.x * 32;
    const int c0 = blockIdx.y * 32;
    const float* src = in + (size_t)n * CH * HW;
    __half* dst = (which ? g_kt : g_qt) + (size_t)n * HW * CH;
    #pragma unroll
    for (int j = threadIdx.y; j < 32; j += 8)
        tile[j][threadIdx.x] = src[(size_t)(c0 + j) * HW + t0 + threadIdx.x];
    __syncthreads();
    #pragma unroll
    for (int j = threadIdx.y; j < 32; j += 8)
        dst[(size_t)(t0 + j) * CH + c0 + threadIdx.x] = __float2half(tile[threadIdx.x][j]);
}

// straight fp32 -> fp16 convert (V), coalesced
__global__ void convert_f32f16(const float* __restrict__ in) {
    int i = blockIdx.x * blockDim.x + threadIdx.x;   // x4 elements
    float4 f = reinterpret_cast<const float4*>(in)[i];
    __half2* o = reinterpret_cast<__half2*>(g_vh);
    o[2 * i]     = __floats2half2_rn(f.x, f.y);
    o[2 * i + 1] = __floats2half2_rn(f.z, f.w);
}

// ---------------- attention kernel ----------------

__device__ __forceinline__ void mma16816(float c[4], const uint32_t a[4],
                                         uint32_t b0, uint32_t b1) {
    asm volatile(
        "mma.sync.aligned.m16n8k16.row.col.f32.f16.f16.f32 "
        "{%0,%1,%2,%3}, {%4,%5,%6,%7}, {%8,%9}, {%0,%1,%2,%3};\n"
        : "+f"(c[0]), "+f"(c[1]), "+f"(c[2]), "+f"(c[3])
        : "r"(a[0]), "r"(a[1]), "r"(a[2]), "r"(a[3]), "r"(b0), "r"(b1));
}

__device__ __forceinline__ float ex2(float x) {
    float y;
    asm("ex2.approx.ftz.f32 %0, %1;" : "=f"(y) : "f"(x));
    return y;
}

__device__ __forceinline__ uint32_t packh2(float a, float b) {
    __half2 h = __floats2half2_rn(a, b);
    return *reinterpret_cast<uint32_t*>(&h);
}

__device__ __forceinline__ void cpa16(uint32_t dst, const __half* src) {
    asm volatile("cp.async.cg.shared.global [%0], [%1], 16;" :: "r"(dst), "l"(src));
}
__device__ __forceinline__ void cpa_commit() {
    asm volatile("cp.async.commit_group;" ::: "memory");
}
template <int N>
__device__ __forceinline__ void cpa_wait() {
    asm volatile("cp.async.wait_group %0;" :: "n"(N) : "memory");
}

__global__ void __launch_bounds__(THREADS, 1)
attn_kernel(float* __restrict__ Og) {
    extern __shared__ __half smem[];
    __half* Qs  = smem;                       // [BT][QK_PITCH]
    __half* Ks0 = Qs  + BT * QK_PITCH;        // [BS][QK_PITCH] x2
    __half* Ks1 = Ks0 + BS * QK_PITCH;
    __half* Vs0 = Ks1 + BS * QK_PITCH;        // [CH][V_PITCH] x2
    __half* Vs1 = Vs0 + CH * V_PITCH;

    const int n  = blockIdx.y;
    const int t0 = blockIdx.x * BT;
    const __half* qtb = g_qt + (size_t)n * HW * CH;
    const __half* ktb = g_kt + (size_t)n * HW * CH;
    const __half* vhb = g_vh + (size_t)n * CH * HW;
    float* ob = Og + (size_t)n * CH * HW;

    const int tid  = threadIdx.x;
    const int warp = tid >> 5;
    const int lane = tid & 31;
    const int g    = lane >> 2;
    const int tq   = lane & 3;

    const uint32_t qs_u32 = (uint32_t)__cvta_generic_to_shared(Qs);
    const uint32_t ks_u32[2] = {(uint32_t)__cvta_generic_to_shared(Ks0),
                                (uint32_t)__cvta_generic_to_shared(Ks1)};
    const uint32_t vs_u32[2] = {(uint32_t)__cvta_generic_to_shared(Vs0),
                                (uint32_t)__cvta_generic_to_shared(Vs1)};

    // ---- prologue: async-copy Q tile + K/V tile 0 (one group) ----
    for (int ch = tid; ch < BT * 16; ch += THREADS) {          // Q: 128 rows x 16 chunks
        int r = ch >> 4, x = ch & 15;
        cpa16(qs_u32 + (uint32_t)(r * QK_PITCH * 2 + x * 16),
              qtb + (size_t)(t0 + r) * CH + x * 8);
    }
    for (int ch = tid; ch < BS * 16; ch += THREADS) {          // K tile 0
        int r = ch >> 4, x = ch & 15;
        cpa16(ks_u32[0] + (uint32_t)(r * QK_PITCH * 2 + x * 16),
              ktb + (size_t)r * CH + x * 8);
    }
    for (int ch = tid; ch < CH * 8; ch += THREADS) {           // V tile 0
        int r = ch >> 3, x = ch & 7;
        cpa16(vs_u32[0] + (uint32_t)(r * V_PITCH * 2 + x * 16),
              vhb + (size_t)r * HW + x * 8);
    }
    cpa_commit();
    cpa_wait<0>();
    __syncthreads();

    // ---- Q A-fragments resident in registers ----
    uint32_t qa[8][4];
    {
        int r = warp * 16 + g;
        #pragma unroll
        for (int kk = 0; kk < 8; kk++) {
            int c0 = kk * 16 + tq * 2;
            qa[kk][0] = *reinterpret_cast<const uint32_t*>(&Qs[r * QK_PITCH + c0]);
            qa[kk][1] = *reinterpret_cast<const uint32_t*>(&Qs[(r + 8) * QK_PITCH + c0]);
            qa[kk][2] = *reinterpret_cast<const uint32_t*>(&Qs[r * QK_PITCH + c0 + 8]);
            qa[kk][3] = *reinterpret_cast<const uint32_t*>(&Qs[(r + 8) * QK_PITCH + c0 + 8]);
        }
    }

    const float kf = 0.12751742562077963f;   // log2(e)/sqrt(128)

    float mrow0 = -1e30f, mrow1 = -1e30f;
    float lrow0 = 0.f, lrow1 = 0.f;
    float o[16][4];
    #pragma unroll
    for (int j = 0; j < 16; j++)
        o[j][0] = o[j][1] = o[j][2] = o[j][3] = 0.f;

    for (int it = 0; it < NTILES; it++) {
        const int cur = it & 1;
        // ---- issue async copy of next tile into the other buffer ----
        if (it + 1 < NTILES) {
            const int nxt = cur ^ 1;
            const int s1 = (it + 1) * BS;
            for (int ch = tid; ch < BS * 16; ch += THREADS) {
                int r = ch >> 4, x = ch & 15;
                cpa16(ks_u32[nxt] + (uint32_t)(r * QK_PITCH * 2 + x * 16),
                      ktb + (size_t)(s1 + r) * CH + x * 8);
            }
            for (int ch = tid; ch < CH * 8; ch += THREADS) {
                int r = ch >> 3, x = ch & 7;
                cpa16(vs_u32[nxt] + (uint32_t)(r * V_PITCH * 2 + x * 16),
                      vhb + (size_t)r * HW + s1 + x * 8);
            }
            cpa_commit();
            cpa_wait<1>();     // current tile's group has drained
        } else {
            cpa_wait<0>();
        }
        __syncthreads();        // current buffer visible to all warps

        const __half* Ksc = cur ? Ks1 : Ks0;
        const __half* Vsc = cur ? Vs1 : Vs0;

        // ---- S = Q.K^T  (scalar-LDS fed; proven fastest variant) ----
        float sacc[8][4];
        #pragma unroll
        for (int j = 0; j < 8; j++)
            sacc[j][0] = sacc[j][1] = sacc[j][2] = sacc[j][3] = 0.f;

        #pragma unroll
        for (int kk = 0; kk < 8; kk++) {
            #pragma unroll
            for (int j = 0; j < 8; j++) {
                const __half* brow = &Ksc[(8 * j + g) * QK_PITCH + 16 * kk + 2 * tq];
                uint32_t b0 = *reinterpret_cast<const uint32_t*>(brow);
                uint32_t b1 = *reinterpret_cast<const uint32_t*>(brow + 8);
                mma16816(sacc[j], qa[kk], b0, b1);
            }
        }

        // ---- online softmax ----
        float mx0 = -1e30f, mx1 = -1e30f;
        #pragma unroll
        for (int j = 0; j < 8; j++) {
            mx0 = fmaxf(mx0, fmaxf(sacc[j][0], sacc[j][1]));
            mx1 = fmaxf(mx1, fmaxf(sacc[j][2], sacc[j][3]));
        }
        mx0 = fmaxf(mx0, __shfl_xor_sync(0xffffffffu, mx0, 1));
        mx0 = fmaxf(mx0, __shfl_xor_sync(0xffffffffu, mx0, 2));
        mx1 = fmaxf(mx1, __shfl_xor_sync(0xffffffffu, mx1, 1));
        mx1 = fmaxf(mx1, __shfl_xor_sync(0xffffffffu, mx1, 2));

        float mn0 = fmaxf(mrow0, mx0);
        float mn1 = fmaxf(mrow1, mx1);
        float alpha0 = ex2(kf * (mrow0 - mn0));
        float alpha1 = ex2(kf * (mrow1 - mn1));
        mrow0 = mn0; mrow1 = mn1;

        float rs0 = 0.f, rs1 = 0.f;
        #pragma unroll
        for (int j = 0; j < 8; j++) {
            sacc[j][0] = ex2(kf * (sacc[j][0] - mn0));
            sacc[j][1] = ex2(kf * (sacc[j][1] - mn0));
            sacc[j][2] = ex2(kf * (sacc[j][2] - mn1));
            sacc[j][3] = ex2(kf * (sacc[j][3] - mn1));
            rs0 += sacc[j][0] + sacc[j][1];
            rs1 += sacc[j][2] + sacc[j][3];
        }
        rs0 += __shfl_xor_sync(0xffffffffu, rs0, 1);
        rs0 += __shfl_xor_sync(0xffffffffu, rs0, 2);
        rs1 += __shfl_xor_sync(0xffffffffu, rs1, 1);
        rs1 += __shfl_xor_sync(0xffffffffu, rs1, 2);
        lrow0 = lrow0 * alpha0 + rs0;
        lrow1 = lrow1 * alpha1 + rs1;

        #pragma unroll
        for (int j = 0; j < 16; j++) {
            o[j][0] *= alpha0; o[j][1] *= alpha0;
            o[j][2] *= alpha1; o[j][3] *= alpha1;
        }

        // ---- P -> A-fragments ----
        uint32_t pa[4][4];
        #pragma unroll
        for (int kk = 0; kk < 4; kk++) {
            pa[kk][0] = packh2(sacc[2 * kk][0],     sacc[2 * kk][1]);
            pa[kk][1] = packh2(sacc[2 * kk][2],     sacc[2 * kk][3]);
            pa[kk][2] = packh2(sacc[2 * kk + 1][0], sacc[2 * kk + 1][1]);
            pa[kk][3] = packh2(sacc[2 * kk + 1][2], sacc[2 * kk + 1][3]);
        }

        // ---- O += P.V ----
        #pragma unroll
        for (int kk = 0; kk < 4; kk++) {
            #pragma unroll
            for (int je = 0; je < 16; je++) {
                const __half* brow = &Vsc[(8 * je + g) * V_PITCH + 16 * kk + 2 * tq];
                uint32_t b0 = *reinterpret_cast<const uint32_t*>(brow);
                uint32_t b1 = *reinterpret_cast<const uint32_t*>(brow + 8);
                mma16816(o[je], pa[kk], b0, b1);
            }
        }
        __syncthreads();   // all reads of cur done before it's overwritten at it+1
    }

    // ---- normalize + transposed store out[n][e][t] ----
    float inv0 = 1.f / lrow0;
    float inv1 = 1.f / lrow1;
    int r = t0 + warp * 16 + g;
    #pragma unroll
    for (int je = 0; je < 16; je++) {
        int e = 8 * je + 2 * tq;
        ob[(size_t)e * HW + r]           = o[je][0] * inv0;
        ob[(size_t)(e + 1) * HW + r]     = o[je][1] * inv0;
        ob[(size_t)e * HW + r + 8]       = o[je][2] * inv1;
        ob[(size_t)(e + 1) * HW + r + 8] = o[je][3] * inv1;
    }
}

extern "C" void kernel_launch(void* const* d_in, const int* in_sizes, int n_in,
                              void* d_out, int out_size) {
    const float* k = (const float*)d_in[0];
    const float* q = (const float*)d_in[1];
    const float* v = (const float*)d_in[2];
    float* o = (float*)d_out;

    // pre-pass: transpose+convert Q,K; convert V
    dim3 tb(32, 8);
    dim3 tg(HW / 32, CH / 32, NB);
    transpose_f32f16<<<tg, tb>>>(q, 0);
    transpose_f32f16<<<tg, tb>>>(k, 1);
    convert_f32f16<<<(NB * CH * HW / 4) / 256, 256>>>(v);

    size_t smem_bytes = (size_t)(BT * QK_PITCH + 2 * BS * QK_PITCH + 2 * CH * V_PITCH)
                        * sizeof(__half);
    cudaFuncSetAttribute((const void*)attn_kernel,
                         cudaFuncAttributeMaxDynamicSharedMemorySize, (int)smem_bytes);
    dim3 grid(HW / BT, NB);
    attn_kernel<<<grid, THREADS, (int)smem_bytes>>>(o);
}